// round 9
// baseline (speedup 1.0000x reference)
#include <cuda_runtime.h>
#include <cuda_bf16.h>
#include <math.h>
#include <stdint.h>

#define Lseq 2048
#define BHn  8

// scratch (allocation-free rule: __device__ globals)
__device__ float g_v[BHn * Lseq * 64];
__device__ float g_ctx[BHn * Lseq * 64];
__device__ float g_sumexp[BHn * Lseq];          // sumexp -> lse (in place)
__device__ float g_colsum[BHn * 64];            // per-(bh) column sums of v
__device__ __nv_bfloat16 g_qh[BHn * Lseq * 64];
__device__ __nv_bfloat16 g_ql[BHn * Lseq * 64];
__device__ __nv_bfloat16 g_kh[BHn * Lseq * 64];
__device__ __nv_bfloat16 g_kl[BHn * Lseq * 64];
__device__ __nv_bfloat16 g_wth[3 * 128 * 512];  // W^T hi  [which][n][k]
__device__ __nv_bfloat16 g_wtl[3 * 128 * 512];  // W^T lo
__device__ __nv_bfloat16 g_woth[512 * 128];     // Wo^T hi [n][k]
__device__ __nv_bfloat16 g_wotl[512 * 128];     // Wo^T lo
__device__ __nv_bfloat16 g_vth[BHn * 64 * Lseq]; // V^T hi [bh][d][j]
__device__ __nv_bfloat16 g_vtl[BHn * 64 * Lseq]; // V^T lo

__device__ __forceinline__ uint32_t smem_u32(const void* p) {
    uint32_t a;
    asm("{ .reg .u64 t; cvta.to.shared.u64 t, %1; cvt.u32.u64 %0, t; }" : "=r"(a) : "l"(p));
    return a;
}
__device__ __forceinline__ void ldsm_x4(uint32_t* r, uint32_t addr) {
    asm volatile("ldmatrix.sync.aligned.m8n8.x4.shared.b16 {%0,%1,%2,%3}, [%4];"
        : "=r"(r[0]), "=r"(r[1]), "=r"(r[2]), "=r"(r[3]) : "r"(addr));
}
__device__ __forceinline__ void mma_bf16(float* c, const uint32_t* a, const uint32_t* b) {
    asm volatile("mma.sync.aligned.m16n8k16.row.col.f32.bf16.bf16.f32 "
        "{%0,%1,%2,%3}, {%4,%5,%6,%7}, {%8,%9}, {%0,%1,%2,%3};"
        : "+f"(c[0]), "+f"(c[1]), "+f"(c[2]), "+f"(c[3])
        : "r"(a[0]), "r"(a[1]), "r"(a[2]), "r"(a[3]), "r"(b[0]), "r"(b[1]));
}
__device__ __forceinline__ uint32_t pack_bf2(float a, float b) {
    __nv_bfloat162 t;
    t.x = __float2bfloat16(a); t.y = __float2bfloat16(b);
    return *(uint32_t*)&t;
}
__device__ __forceinline__ void split4(float4 x, uint2* hi, uint2* lo) {
    __nv_bfloat16 hx = __float2bfloat16(x.x), hy = __float2bfloat16(x.y);
    __nv_bfloat16 hz = __float2bfloat16(x.z), hw = __float2bfloat16(x.w);
    __nv_bfloat162 h01; h01.x = hx; h01.y = hy;
    __nv_bfloat162 h23; h23.x = hz; h23.y = hw;
    hi->x = *(uint32_t*)&h01; hi->y = *(uint32_t*)&h23;
    __nv_bfloat162 l01, l23;
    l01.x = __float2bfloat16(x.x - __bfloat162float(hx));
    l01.y = __float2bfloat16(x.y - __bfloat162float(hy));
    l23.x = __float2bfloat16(x.z - __bfloat162float(hz));
    l23.y = __float2bfloat16(x.w - __bfloat162float(hw));
    lo->x = *(uint32_t*)&l01; lo->y = *(uint32_t*)&l23;
}

// ---------------------------------------------------------------------------
__global__ void zero_kernel(float* __restrict__ sumexp, float* __restrict__ colsum)
{
    if (blockIdx.x < 16) {
        int g = blockIdx.x * 256 + threadIdx.x;
        ((float4*)sumexp)[g] = make_float4(0.f, 0.f, 0.f, 0.f);
    } else if (threadIdx.x < 128) {
        ((float4*)colsum)[threadIdx.x] = make_float4(0.f, 0.f, 0.f, 0.f);
    }
}

// ---------------------------------------------------------------------------
// Weight prep: W [512][128] fp32 -> W^T hi/lo bf16 [which][128 n][512 k].
// ---------------------------------------------------------------------------
__global__ void wt_kernel(const float* __restrict__ Wq, const float* __restrict__ Wk,
                          const float* __restrict__ Wv,
                          __nv_bfloat16* __restrict__ wth, __nv_bfloat16* __restrict__ wtl)
{
    __shared__ float sm[32][132];
    const int which = blockIdx.y;
    const float* W = which == 0 ? Wq : (which == 1 ? Wk : Wv);
    const int k0 = blockIdx.x * 32;
    const int t = threadIdx.x;
    #pragma unroll
    for (int l = 0; l < 8; l++) {
        int u = t + l * 128;
        int k = u >> 5, n4 = u & 31;
        float4 w = *(const float4*)&W[(size_t)(k0 + k) * 128 + n4 * 4];
        sm[k][n4*4+0] = w.x; sm[k][n4*4+1] = w.y;
        sm[k][n4*4+2] = w.z; sm[k][n4*4+3] = w.w;
    }
    __syncthreads();
    uint32_t hw[16], lw[16];
    #pragma unroll
    for (int kk = 0; kk < 32; kk += 2) {
        float a = sm[kk][t], b = sm[kk+1][t];
        __nv_bfloat16 ha = __float2bfloat16(a), hb = __float2bfloat16(b);
        hw[kk>>1] = pack_bf2(a, b);
        lw[kk>>1] = pack_bf2(a - __bfloat162float(ha), b - __bfloat162float(hb));
    }
    size_t base = ((size_t)which * 128 + t) * 512 + k0;
    #pragma unroll
    for (int s = 0; s < 4; s++) {
        *(uint4*)&wth[base + s*8] = *(uint4*)&hw[s*4];
        *(uint4*)&wtl[base + s*8] = *(uint4*)&lw[s*4];
    }
}

// ---------------------------------------------------------------------------
// Wo prep: Wo [128 k][512 n] fp32 -> Wo^T hi/lo bf16 [512 n][128 k].
// ---------------------------------------------------------------------------
__global__ void wo_kernel(const float* __restrict__ Wo,
                          __nv_bfloat16* __restrict__ woth, __nv_bfloat16* __restrict__ wotl)
{
    __shared__ float sm[128][33];
    const int n0 = blockIdx.x * 32;
    const int tid = threadIdx.x;
    #pragma unroll
    for (int l = 0; l < 16; l++) {
        int u = tid + l * 256;
        int k = u >> 5, n = u & 31;
        sm[k][n] = Wo[(size_t)k * 512 + n0 + n];
    }
    __syncthreads();
    #pragma unroll
    for (int l = 0; l < 16; l++) {
        int u = tid + l * 256;
        int n = u >> 7, k = u & 127;
        float v = sm[k][n];
        __nv_bfloat16 h = __float2bfloat16(v);
        woth[(size_t)(n0 + n) * 128 + k] = h;
        wotl[(size_t)(n0 + n) * 128 + k] = __float2bfloat16(v - __bfloat162float(h));
    }
}

// ---------------------------------------------------------------------------
// QKV projection via mma.sync bf16 3-term split. M=8192, K=512, N=128.
// ---------------------------------------------------------------------------
__global__ __launch_bounds__(256, 2) void proj_mma_kernel(
    const float* __restrict__ Q, const float* __restrict__ K, const float* __restrict__ V,
    const __nv_bfloat16* __restrict__ wth, const __nv_bfloat16* __restrict__ wtl,
    const float* __restrict__ bq, const float* __restrict__ bk, const float* __restrict__ bv,
    __nv_bfloat16* __restrict__ qh, __nv_bfloat16* __restrict__ ql,
    __nv_bfloat16* __restrict__ kh, __nv_bfloat16* __restrict__ kl,
    float* __restrict__ gv)
{
    extern __shared__ char smem[];
    const int which = blockIdx.y;
    const float* X    = which == 0 ? Q  : (which == 1 ? K  : V);
    const float* bias = which == 0 ? bq : (which == 1 ? bk : bv);
    const int r0 = blockIdx.x * 128;
    const int tid = threadIdx.x, wid = tid >> 5, lid = tid & 31;
    const int wm = wid & 3, wn = wid >> 2;

    char* tXH = smem;              // 128 rows x 144B
    char* tXL = smem + 18432;
    char* tWH = smem + 36864;      // 128 n-rows x 144B
    char* tWL = smem + 55296;
    const uint32_t sXH = smem_u32(tXH), sXL = smem_u32(tXL);
    const uint32_t sWH = smem_u32(tWH), sWL = smem_u32(tWL);

    const uint32_t aOff = (uint32_t)((wm * 32 + (lid & 15)) * 144 + ((lid >> 4) << 4));
    const uint32_t bOff = (uint32_t)((wn * 64 + ((lid & 16) >> 1) + (lid & 7)) * 144
                                     + ((lid & 8) << 1));
    float acc[2][8][4] = {};

    for (int k0 = 0; k0 < 512; k0 += 64) {
        #pragma unroll
        for (int l = 0; l < 8; l++) {
            int u = tid + l * 256;
            int row = u >> 4, k4 = u & 15;
            float4 x = *(const float4*)&X[(size_t)(r0 + row) * 512 + k0 + k4 * 4];
            uint2 hi, lo; split4(x, &hi, &lo);
            *(uint2*)(tXH + row * 144 + k4 * 8) = hi;
            *(uint2*)(tXL + row * 144 + k4 * 8) = lo;
        }
        #pragma unroll
        for (int l = 0; l < 4; l++) {
            int u = tid + l * 256;
            int n = u >> 3, c = u & 7;
            size_t gidx = ((size_t)which * 128 + n) * 512 + k0 + c * 8;
            *(float4*)(tWH + n * 144 + c * 16) = *(const float4*)&wth[gidx];
            *(float4*)(tWL + n * 144 + c * 16) = *(const float4*)&wtl[gidx];
        }
        __syncthreads();

        #pragma unroll
        for (int ks = 0; ks < 4; ks++) {
            uint32_t ah[2][4], al[2][4], bh[4][4], bl[4][4];
            ldsm_x4(ah[0], sXH + aOff + ks * 32);
            ldsm_x4(ah[1], sXH + aOff + ks * 32 + 16 * 144);
            ldsm_x4(al[0], sXL + aOff + ks * 32);
            ldsm_x4(al[1], sXL + aOff + ks * 32 + 16 * 144);
            #pragma unroll
            for (int np = 0; np < 4; np++) {
                ldsm_x4(bh[np], sWH + bOff + ks * 32 + np * 16 * 144);
                ldsm_x4(bl[np], sWL + bOff + ks * 32 + np * 16 * 144);
            }
            #pragma unroll
            for (int mi = 0; mi < 2; mi++)
                #pragma unroll
                for (int np = 0; np < 4; np++) {
                    mma_bf16(acc[mi][np*2],   ah[mi], &bh[np][0]);
                    mma_bf16(acc[mi][np*2+1], ah[mi], &bh[np][2]);
                    mma_bf16(acc[mi][np*2],   ah[mi], &bl[np][0]);
                    mma_bf16(acc[mi][np*2+1], ah[mi], &bl[np][2]);
                    mma_bf16(acc[mi][np*2],   al[mi], &bh[np][0]);
                    mma_bf16(acc[mi][np*2+1], al[mi], &bh[np][2]);
                }
        }
        __syncthreads();
    }

    const int g = lid >> 2, qid = lid & 3;
    #pragma unroll
    for (int mi = 0; mi < 2; mi++) {
        #pragma unroll
        for (int half = 0; half < 2; half++) {
            int r = r0 + wm * 32 + mi * 16 + half * 8 + g;
            int b = r >> 11, ii = r & 2047;
            #pragma unroll
            for (int ni = 0; ni < 8; ni++) {
                int col = wn * 64 + ni * 8 + qid * 2;
                float v0 = acc[mi][ni][half*2+0] + bias[col];
                float v1 = acc[mi][ni][half*2+1] + bias[col+1];
                int h = col >> 6, dd = col & 63;
                size_t idx = (((size_t)(b*2 + h)) * 2048 + ii) * 64 + dd;
                if (which == 2) {
                    *(float2*)&gv[idx] = make_float2(v0, v1);
                } else {
                    __nv_bfloat16 h0 = __float2bfloat16(v0), h1 = __float2bfloat16(v1);
                    uint32_t hp = pack_bf2(v0, v1);
                    uint32_t lp = pack_bf2(v0 - __bfloat162float(h0), v1 - __bfloat162float(h1));
                    __nv_bfloat16* ph = (which == 0 ? qh : kh);
                    __nv_bfloat16* pl = (which == 0 ? ql : kl);
                    *(uint32_t*)&ph[idx] = hp;
                    *(uint32_t*)&pl[idx] = lp;
                }
            }
        }
    }
}

// ---------------------------------------------------------------------------
// V transpose + split + fused colsum.
// ---------------------------------------------------------------------------
__global__ void vt_kernel(const float* __restrict__ gv,
                          __nv_bfloat16* __restrict__ vth, __nv_bfloat16* __restrict__ vtl,
                          float* __restrict__ colsum)
{
    __shared__ float sm[128][68];
    __shared__ float red[256];
    const int bh = blockIdx.y;
    const int j0 = blockIdx.x * 128;
    const int tid = threadIdx.x;
    const float* v = gv + (size_t)bh * 2048 * 64;
    #pragma unroll
    for (int l = 0; l < 8; l++) {
        int u = tid + l * 256;
        int j = u >> 4, d4 = u & 15;
        float4 x = *(const float4*)&v[(size_t)(j0 + j) * 64 + d4 * 4];
        sm[j][d4*4+0] = x.x; sm[j][d4*4+1] = x.y;
        sm[j][d4*4+2] = x.z; sm[j][d4*4+3] = x.w;
    }
    __syncthreads();
    #pragma unroll
    for (int l = 0; l < 8; l++) {
        int u = tid + l * 256;
        int d = u >> 5, j4 = u & 31;
        float4 x = make_float4(sm[j4*4+0][d], sm[j4*4+1][d], sm[j4*4+2][d], sm[j4*4+3][d]);
        uint2 hi, lo; split4(x, &hi, &lo);
        size_t idx = ((size_t)bh * 64 + d) * 2048 + j0 + j4 * 4;
        *(uint2*)&vth[idx] = hi;
        *(uint2*)&vtl[idx] = lo;
    }
    {
        const int d = tid & 63, part = tid >> 6;
        float s = 0.f;
        #pragma unroll 8
        for (int j = part * 32; j < part * 32 + 32; j++) s += sm[j][d];
        red[tid] = s;
        __syncthreads();
        if (tid < 64)
            atomicAdd(&colsum[bh * 64 + tid],
                      red[tid] + red[tid+64] + red[tid+128] + red[tid+192]);
    }
}

// ---------------------------------------------------------------------------
// mma.sync scores; fragments loaded once per k-step, 3 terms from registers.
// ---------------------------------------------------------------------------
__global__ __launch_bounds__(256, 2) void scores_mma_kernel(
    const __nv_bfloat16* __restrict__ gqh, const __nv_bfloat16* __restrict__ gql,
    const __nv_bfloat16* __restrict__ gkh, const __nv_bfloat16* __restrict__ gkl,
    const int* __restrict__ mask, float* __restrict__ attn, float* __restrict__ sumexp)
{
    extern __shared__ char smem[];
    const int tid = threadIdx.x, wid = tid >> 5, lid = tid & 31;
    const int bh = blockIdx.z, b = bh >> 1;
    const int i0 = blockIdx.x * 128, j0 = blockIdx.y * 128;
    const int wm = wid & 3, wn = wid >> 2;

    char* tQH = smem;
    char* tQL = smem + 18432;
    char* tKH = smem + 36864;
    char* tKL = smem + 55296;
    int*  smk = (int*)(smem + 73728);

    {
        const float4* s0 = (const float4*)(gqh + ((size_t)bh * 2048 + i0) * 64);
        const float4* s1 = (const float4*)(gql + ((size_t)bh * 2048 + i0) * 64);
        const float4* s2 = (const float4*)(gkh + ((size_t)bh * 2048 + j0) * 64);
        const float4* s3 = (const float4*)(gkl + ((size_t)bh * 2048 + j0) * 64);
        #pragma unroll
        for (int l = 0; l < 4; l++) {
            int u = tid + l * 256;
            int row = u >> 3, ch = u & 7;
            int off = row * 144 + ch * 16;
            *(float4*)(tQH + off) = s0[u];
            *(float4*)(tQL + off) = s1[u];
            *(float4*)(tKH + off) = s2[u];
            *(float4*)(tKL + off) = s3[u];
        }
    }
    if (tid < 128) smk[tid] = mask[b * 2048 + j0 + tid];
    __syncthreads();

    const uint32_t aOff = (uint32_t)((wm * 32 + (lid & 15)) * 144 + ((lid >> 4) << 4));
    const uint32_t bOff = (uint32_t)((wn * 64 + ((lid & 16) >> 1) + (lid & 7)) * 144
                                     + ((lid & 8) << 1));
    const uint32_t sQH = smem_u32(tQH), sQL = smem_u32(tQL);
    const uint32_t sKH = smem_u32(tKH), sKL = smem_u32(tKL);

    float acc[2][8][4] = {};
    #pragma unroll
    for (int ks = 0; ks < 4; ks++) {
        uint32_t ah[2][4], al[2][4], bhf[4][4], blf[4][4];
        ldsm_x4(ah[0], sQH + aOff + ks * 32);
        ldsm_x4(ah[1], sQH + aOff + ks * 32 + 16 * 144);
        ldsm_x4(al[0], sQL + aOff + ks * 32);
        ldsm_x4(al[1], sQL + aOff + ks * 32 + 16 * 144);
        #pragma unroll
        for (int np = 0; np < 4; np++) {
            ldsm_x4(bhf[np], sKH + bOff + ks * 32 + np * 16 * 144);
            ldsm_x4(blf[np], sKL + bOff + ks * 32 + np * 16 * 144);
        }
        #pragma unroll
        for (int mi = 0; mi < 2; mi++)
            #pragma unroll
            for (int np = 0; np < 4; np++) {
                mma_bf16(acc[mi][np*2],   ah[mi], &bhf[np][0]);
                mma_bf16(acc[mi][np*2+1], ah[mi], &bhf[np][2]);
                mma_bf16(acc[mi][np*2],   ah[mi], &blf[np][0]);
                mma_bf16(acc[mi][np*2+1], ah[mi], &blf[np][2]);
                mma_bf16(acc[mi][np*2],   al[mi], &bhf[np][0]);
                mma_bf16(acc[mi][np*2+1], al[mi], &bhf[np][2]);
            }
    }
    __syncthreads();

    float* buf = (float*)smem;             // [128][132]
    const int g = lid >> 2, qid = lid & 3;
    float rs[2][2] = {};
    #pragma unroll
    for (int mi = 0; mi < 2; mi++) {
        const int row0 = wm * 32 + mi * 16 + g;
        #pragma unroll
        for (int ni = 0; ni < 8; ni++) {
            const int col = wn * 64 + ni * 8 + qid * 2;
            const int m0 = smk[col], m1 = smk[col + 1];
            float v0 = acc[mi][ni][0], v1 = acc[mi][ni][1];
            float v2 = acc[mi][ni][2], v3 = acc[mi][ni][3];
            v0 = 10.0f - 20.0f / (__expf(v0 * 0.25f) + 1.0f);
            v1 = 10.0f - 20.0f / (__expf(v1 * 0.25f) + 1.0f);
            v2 = 10.0f - 20.0f / (__expf(v2 * 0.25f) + 1.0f);
            v3 = 10.0f - 20.0f / (__expf(v3 * 0.25f) + 1.0f);
            if (m0) { v0 = -10.0f; v2 = -10.0f; }
            if (m1) { v1 = -10.0f; v3 = -10.0f; }
            rs[mi][0] += __expf(v0) + __expf(v1);
            rs[mi][1] += __expf(v2) + __expf(v3);
            *(float2*)&buf[row0 * 132 + col]       = make_float2(v0, v1);
            *(float2*)&buf[(row0 + 8) * 132 + col] = make_float2(v2, v3);
        }
    }
    #pragma unroll
    for (int mi = 0; mi < 2; mi++)
        #pragma unroll
        for (int hl = 0; hl < 2; hl++) {
            float r = rs[mi][hl];
            r += __shfl_xor_sync(0xffffffffu, r, 1);
            r += __shfl_xor_sync(0xffffffffu, r, 2);
            if (qid == 0)
                atomicAdd(&sumexp[bh * 2048 + i0 + wm * 32 + mi * 16 + hl * 8 + g], r);
        }
    __syncthreads();

    #pragma unroll
    for (int l = 0; l < 16; l++) {
        int idx = tid + l * 256;
        int row = idx >> 5, c4 = idx & 31;
        float4 v = *(const float4*)&buf[row * 132 + c4 * 4];
        *(float4*)(attn + ((size_t)bh * 2048 + i0 + row) * 2048 + j0 + c4 * 4) = v;
    }
}

// ---------------------------------------------------------------------------
// lse in-place (sumexp -> log(sumexp)) + ctx init = -lse * colsum.
// grid 1024, 256 thr; each block 16 rows of (bh,i).
// ---------------------------------------------------------------------------
__global__ void ctx_init_kernel(float* __restrict__ sumexp,
                                const float* __restrict__ colsum,
                                float* __restrict__ ctx)
{
    const int tid = threadIdx.x;
    const int row = blockIdx.x * 16 + (tid >> 4);   // 0..16383
    const int f4  = tid & 15;
    const int bh  = row >> 11;
    float lse = __logf(sumexp[row]);
    if (f4 == 0) sumexp[row] = lse;                 // safe: all lanes read before store
    float4 cs = *(const float4*)&colsum[bh * 64 + f4 * 4];
    *(float4*)&ctx[(size_t)row * 64 + f4 * 4] =
        make_float4(-lse * cs.x, -lse * cs.y, -lse * cs.z, -lse * cs.w);
}

// ---------------------------------------------------------------------------
// AV via mma.sync bf16 3-term, 8-way k-split, atomicAdd into pre-init ctx.
// attn -> x - lse normalize write-back fused. grid (16, 8, 8) = 1024 CTAs.
// ---------------------------------------------------------------------------
__global__ __launch_bounds__(256, 2) void av_mma_kernel(
    float* __restrict__ attn,
    const __nv_bfloat16* __restrict__ vth, const __nv_bfloat16* __restrict__ vtl,
    const float* __restrict__ lse, float* __restrict__ ctx)
{
    extern __shared__ char smem[];
    const int bh = blockIdx.z;
    const int ksplit = blockIdx.y;
    const int i0 = blockIdx.x * 128;
    const int tid = threadIdx.x, wid = tid >> 5, lid = tid & 31;
    const int wm = wid & 3, wn = wid >> 2;

    char* tAH = smem;               // 128 x 144B
    char* tAL = smem + 18432;
    char* tBH = smem + 36864;       // 64 x 144B
    char* tBL = smem + 46080;
    float* ls = (float*)(smem + 55296);   // 128
    const uint32_t sAH = smem_u32(tAH), sAL = smem_u32(tAL);
    const uint32_t sBH = smem_u32(tBH), sBL = smem_u32(tBL);

    if (tid < 128) ls[tid] = lse[bh * 2048 + i0 + tid];
    __syncthreads();

    float* a = attn + (size_t)bh * 2048 * 2048;
    const __nv_bfloat16* bh_vt = vth + (size_t)bh * 64 * 2048;
    const __nv_bfloat16* bl_vt = vtl + (size_t)bh * 64 * 2048;

    const uint32_t aOff = (uint32_t)((wm * 32 + (lid & 15)) * 144 + ((lid >> 4) << 4));
    const uint32_t bOff = (uint32_t)((wn * 32 + ((lid & 16) >> 1) + (lid & 7)) * 144
                                     + ((lid & 8) << 1));
    float acc[2][4][4] = {};

    for (int k0 = ksplit * 256; k0 < ksplit * 256 + 256; k0 += 64) {
        #pragma unroll
        for (int l = 0; l < 8; l++) {
            int u = tid + l * 256;
            int row = u >> 4, j4 = u & 15;
            size_t gi = (size_t)(i0 + row) * 2048 + k0 + j4 * 4;
            float4 x = *(const float4*)&a[gi];
            float lv = ls[row];
            *(float4*)&a[gi] = make_float4(x.x - lv, x.y - lv, x.z - lv, x.w - lv);
            uint2 hi, lo; split4(x, &hi, &lo);
            *(uint2*)(tAH + row * 144 + j4 * 8) = hi;
            *(uint2*)(tAL + row * 144 + j4 * 8) = lo;
        }
        #pragma unroll
        for (int l = 0; l < 2; l++) {
            int u = tid + l * 256;
            int d = u >> 3, c = u & 7;
            size_t gidx = (size_t)d * 2048 + k0 + c * 8;
            *(float4*)(tBH + d * 144 + c * 16) = *(const float4*)&bh_vt[gidx];
            *(float4*)(tBL + d * 144 + c * 16) = *(const float4*)&bl_vt[gidx];
        }
        __syncthreads();

        #pragma unroll
        for (int ks = 0; ks < 4; ks++) {
            uint32_t ah[2][4], al[2][4], bhf[2][4], blf[2][4];
            ldsm_x4(ah[0], sAH + aOff + ks * 32);
            ldsm_x4(ah[1], sAH + aOff + ks * 32 + 16 * 144);
            ldsm_x4(al[0], sAL + aOff + ks * 32);
            ldsm_x4(al[1], sAL + aOff + ks * 32 + 16 * 144);
            ldsm_x4(bhf[0], sBH + bOff + ks * 32);
            ldsm_x4(bhf[1], sBH + bOff + ks * 32 + 16 * 144);
            ldsm_x4(blf[0], sBL + bOff + ks * 32);
            ldsm_x4(blf[1], sBL + bOff + ks * 32 + 16 * 144);
            #pragma unroll
            for (int mi = 0; mi < 2; mi++)
                #pragma unroll
                for (int n2 = 0; n2 < 2; n2++)
                    #pragma unroll
                    for (int p = 0; p < 2; p++) {
                        float* c = acc[mi][n2*2+p];
                        mma_bf16(c, ah[mi], &bhf[n2][p*2]);
                        mma_bf16(c, ah[mi], &blf[n2][p*2]);
                        mma_bf16(c, al[mi], &bhf[n2][p*2]);
                    }
        }
        __syncthreads();
    }

    const int g = lid >> 2, qid = lid & 3;
    #pragma unroll
    for (int mi = 0; mi < 2; mi++) {
        #pragma unroll
        for (int half = 0; half < 2; half++) {
            int rl = wm * 32 + mi * 16 + half * 8 + g;
            size_t rbase = ((size_t)bh * 2048 + i0 + rl) * 64;
            #pragma unroll
            for (int ni = 0; ni < 4; ni++) {
                int col = wn * 32 + ni * 8 + qid * 2;
                atomicAdd(&ctx[rbase + col],     acc[mi][ni][half*2+0]);
                atomicAdd(&ctx[rbase + col + 1], acc[mi][ni][half*2+1]);
            }
        }
    }
}

// ---------------------------------------------------------------------------
// Output proj via mma.sync bf16 3-term. M=8192, K=128 (2 chunks), N=512.
// ---------------------------------------------------------------------------
__global__ __launch_bounds__(256, 2) void out_mma_kernel(
    const float* __restrict__ ctx,
    const __nv_bfloat16* __restrict__ woth, const __nv_bfloat16* __restrict__ wotl,
    const float* __restrict__ bo, float* __restrict__ out)
{
    extern __shared__ char smem[];
    const int r0 = blockIdx.x * 128, c0 = blockIdx.y * 128;
    const int tid = threadIdx.x, wid = tid >> 5, lid = tid & 31;
    const int wm = wid & 3, wn = wid >> 2;

    char* tAH = smem;              // 128 rows x 144B
    char* tAL = smem + 18432;
    char* tBH = smem + 36864;      // 128 n x 144B
    char* tBL = smem + 55296;
    const uint32_t sAH = smem_u32(tAH), sAL = smem_u32(tAL);
    const uint32_t sBH = smem_u32(tBH), sBL = smem_u32(tBL);

    const uint32_t aOff = (uint32_t)((wm * 32 + (lid & 15)) * 144 + ((lid >> 4) << 4));
    const uint32_t bOff = (uint32_t)((wn * 64 + ((lid & 16) >> 1) + (lid & 7)) * 144
                                     + ((lid & 8) << 1));
    float acc[2][8][4] = {};

    for (int h = 0; h < 2; h++) {      // k chunk = head
        #pragma unroll
        for (int l = 0; l < 8; l++) {
            int u = tid + l * 256;
            int row = u >> 4, k4 = u & 15;
            int r = r0 + row;
            int b = r >> 11, ii = r & 2047;
            float4 x = *(const float4*)&ctx[(((size_t)(b*2 + h)) * 2048 + ii) * 64 + k4 * 4];
            uint2 hi, lo; split4(x, &hi, &lo);
            *(uint2*)(tAH + row * 144 + k4 * 8) = hi;
            *(uint2*)(tAL + row * 144 + k4 * 8) = lo;
        }
        #pragma unroll
        for (int l = 0; l < 4; l++) {
            int u = tid + l * 256;
            int n = u >> 3, c = u & 7;
            size_t gidx = (size_t)(c0 + n) * 128 + h * 64 + c * 8;
            *(float4*)(tBH + n * 144 + c * 16) = *(const float4*)&woth[gidx];
            *(float4*)(tBL + n * 144 + c * 16) = *(const float4*)&wotl[gidx];
        }
        __syncthreads();

        #pragma unroll
        for (int ks = 0; ks < 4; ks++) {
            uint32_t ah[2][4], al[2][4], bh[4][4], bl[4][4];
            ldsm_x4(ah[0], sAH + aOff + ks * 32);
            ldsm_x4(ah[1], sAH + aOff + ks * 32 + 16 * 144);
            ldsm_x4(al[0], sAL + aOff + ks * 32);
            ldsm_x4(al[1], sAL + aOff + ks * 32 + 16 * 144);
            #pragma unroll
            for (int np = 0; np < 4; np++) {
                ldsm_x4(bh[np], sBH + bOff + ks * 32 + np * 16 * 144);
                ldsm_x4(bl[np], sBL + bOff + ks * 32 + np * 16 * 144);
            }
            #pragma unroll
            for (int mi = 0; mi < 2; mi++)
                #pragma unroll
                for (int np = 0; np < 4; np++) {
                    mma_bf16(acc[mi][np*2],   ah[mi], &bh[np][0]);
                    mma_bf16(acc[mi][np*2+1], ah[mi], &bh[np][2]);
                    mma_bf16(acc[mi][np*2],   ah[mi], &bl[np][0]);
                    mma_bf16(acc[mi][np*2+1], ah[mi], &bl[np][2]);
                    mma_bf16(acc[mi][np*2],   al[mi], &bh[np][0]);
                    mma_bf16(acc[mi][np*2+1], al[mi], &bh[np][2]);
                }
        }
        __syncthreads();
    }

    const int g = lid >> 2, qid = lid & 3;
    #pragma unroll
    for (int mi = 0; mi < 2; mi++) {
        #pragma unroll
        for (int half = 0; half < 2; half++) {
            int r = r0 + wm * 32 + mi * 16 + half * 8 + g;
            #pragma unroll
            for (int ni = 0; ni < 8; ni++) {
                int col = c0 + wn * 64 + ni * 8 + qid * 2;
                float v0 = acc[mi][ni][half*2+0] + bo[col];
                float v1 = acc[mi][ni][half*2+1] + bo[col+1];
                *(float2*)&out[(size_t)r * 512 + col] = make_float2(v0, v1);
            }
        }
    }
}

// ---------------------------------------------------------------------------
extern "C" void kernel_launch(void* const* d_in, const int* in_sizes, int n_in,
                              void* d_out, int out_size)
{
    const float* Q  = (const float*)d_in[0];
    const float* K  = (const float*)d_in[1];
    const float* V  = (const float*)d_in[2];
    const int*   mask = (const int*)d_in[3];   // bool -> int32 in harness
    const float* Wq = (const float*)d_in[4];
    const float* bq = (const float*)d_in[5];
    const float* Wk = (const float*)d_in[6];
    const float* bk = (const float*)d_in[7];
    const float* Wv = (const float*)d_in[8];
    const float* bv = (const float*)d_in[9];
    const float* Wo = (const float*)d_in[10];
    const float* bo = (const float*)d_in[11];

    float* out  = (float*)d_out;                      // [B, L, 512]
    float* attn = out + (size_t)4 * 2048 * 512;       // [B, H, L, L]

    float *gv, *gctx, *gse, *gcs;
    __nv_bfloat16 *qh, *ql, *kh, *kl, *wth, *wtl, *woth, *wotl, *vth, *vtl;
    cudaGetSymbolAddress((void**)&gv,    g_v);
    cudaGetSymbolAddress((void**)&gctx,  g_ctx);
    cudaGetSymbolAddress((void**)&gse,   g_sumexp);
    cudaGetSymbolAddress((void**)&gcs,   g_colsum);
    cudaGetSymbolAddress((void**)&qh,    g_qh);
    cudaGetSymbolAddress((void**)&ql,    g_ql);
    cudaGetSymbolAddress((void**)&kh,    g_kh);
    cudaGetSymbolAddress((void**)&kl,    g_kl);
    cudaGetSymbolAddress((void**)&wth,   g_wth);
    cudaGetSymbolAddress((void**)&wtl,   g_wtl);
    cudaGetSymbolAddress((void**)&woth,  g_woth);
    cudaGetSymbolAddress((void**)&wotl,  g_wotl);
    cudaGetSymbolAddress((void**)&vth,   g_vth);
    cudaGetSymbolAddress((void**)&vtl,   g_vtl);

    static int smem_set = 0;
    if (!smem_set) {
        cudaFuncSetAttribute(scores_mma_kernel, cudaFuncAttributeMaxDynamicSharedMemorySize, 74240);
        cudaFuncSetAttribute(proj_mma_kernel,   cudaFuncAttributeMaxDynamicSharedMemorySize, 73728);
        cudaFuncSetAttribute(av_mma_kernel,     cudaFuncAttributeMaxDynamicSharedMemorySize, 56064);
        cudaFuncSetAttribute(out_mma_kernel,    cudaFuncAttributeMaxDynamicSharedMemorySize, 73728);
        smem_set = 1;
    }

    zero_kernel<<<17, 256>>>(gse, gcs);
    wt_kernel<<<dim3(16, 3), 128>>>(Wq, Wk, Wv, wth, wtl);
    wo_kernel<<<16, 256>>>(Wo, woth, wotl);
    proj_mma_kernel<<<dim3(64, 3), 256, 73728>>>(Q, K, V, wth, wtl, bq, bk, bv,
                                                 qh, ql, kh, kl, gv);
    vt_kernel<<<dim3(16, 8), 256>>>(gv, vth, vtl, gcs);
    scores_mma_kernel<<<dim3(16, 16, 8), 256, 74240>>>(qh, ql, kh, kl, mask, attn, gse);
    ctx_init_kernel<<<1024, 256>>>(gse, gcs, gctx);
    av_mma_kernel<<<dim3(16, 8, 8), 256, 56064>>>(attn, vth, vtl, gse, gctx);
    out_mma_kernel<<<dim3(64, 4), 256, 73728>>>(gctx, woth, wotl, bo, out);
}